// round 2
// baseline (speedup 1.0000x reference)
#include <cuda_runtime.h>
#include <math.h>

#define BCHW (8*36*256*256)

// ---------------- device scratch (allocation-free rule: __device__ globals) ----
__device__ float g_t[16ull*72ull*65536ull];   // gelu(conv1) per (b,slot): 302 MB
__device__ float g_avg[288];
__device__ float g_max[288];
__device__ int   g_topidx[16];
__device__ float g_topw[16];

// ---------------- pooling: per (b,c) mean + max over 256x256 ----------------
__global__ void pool_kernel(const float* __restrict__ x) {
    int bc = blockIdx.x;                         // 0..287
    const float4* p = reinterpret_cast<const float4*>(x + (size_t)bc * 65536);
    float s = 0.f, m = -3.402823466e38f;
    for (int i = threadIdx.x; i < 16384; i += 256) {
        float4 v = p[i];
        s += (v.x + v.y) + (v.z + v.w);
        m = fmaxf(m, fmaxf(fmaxf(v.x, v.y), fmaxf(v.z, v.w)));
    }
    __shared__ float ss[256], sm2[256];
    ss[threadIdx.x] = s; sm2[threadIdx.x] = m;
    __syncthreads();
    for (int o = 128; o > 0; o >>= 1) {
        if (threadIdx.x < o) {
            ss[threadIdx.x] += ss[threadIdx.x + o];
            sm2[threadIdx.x] = fmaxf(sm2[threadIdx.x], sm2[threadIdx.x + o]);
        }
        __syncthreads();
    }
    if (threadIdx.x == 0) { g_avg[bc] = ss[0] * (1.f/65536.f); g_max[bc] = sm2[0]; }
}

// ---------------- gating MLP + top-2 + loss ----------------
__global__ void gate_kernel(const float* __restrict__ timev,
                            const float* __restrict__ time_w,
                            const float* __restrict__ time_b,
                            const float* __restrict__ w1,
                            const float* __restrict__ b1,
                            const float* __restrict__ w2,
                            const float* __restrict__ b2,
                            float* __restrict__ out, long long out_size) {
    __shared__ float v[8][72];
    __shared__ float h[8][72];
    __shared__ float lg[8][6];
    __shared__ float gates[8][6];
    int tid = threadIdx.x;
    if (tid < 48) gates[tid/6][tid%6] = 0.f;
    for (int i = tid; i < 576; i += 256) {
        int b = i / 72, j = i % 72;
        float a = (j < 36) ? g_avg[b*36 + j] : g_max[b*36 + j - 36];
        float s = time_b[j];
        #pragma unroll
        for (int k = 0; k < 32; k++) s = fmaf(timev[b*32+k], time_w[k*72+j], s);
        v[b][j] = a + s;
    }
    __syncthreads();
    for (int i = tid; i < 576; i += 256) {
        int b = i / 72, j = i % 72;
        float s = b1[j];
        for (int k = 0; k < 72; k++) s = fmaf(v[b][k], w1[k*72+j], s);
        h[b][j] = (s > 0.f) ? s : 0.01f * s;   // LeakyReLU(0.01)
    }
    __syncthreads();
    if (tid < 48) {
        int b = tid / 6, j = tid % 6;
        float s = b2[j];
        for (int k = 0; k < 72; k++) s = fmaf(h[b][k], w2[k*6+j], s);
        lg[b][j] = s;
    }
    __syncthreads();
    if (tid < 8) {
        int b = tid;
        // top-2, stable (lower index wins ties) == lax.top_k order
        float v0 = -3.402823466e38f; int i0 = 0;
        for (int j = 0; j < 6; j++) if (lg[b][j] > v0) { v0 = lg[b][j]; i0 = j; }
        float v1 = -3.402823466e38f; int i1 = 0;
        for (int j = 0; j < 6; j++) if (j != i0 && lg[b][j] > v1) { v1 = lg[b][j]; i1 = j; }
        float e  = expf(v1 - v0);
        float w0 = 1.f / (1.f + e);
        float w1v = e / (1.f + e);
        gates[b][i0] = w0; gates[b][i1] = w1v;
        g_topidx[2*b]   = i0; g_topidx[2*b+1] = i1;
        g_topw[2*b]     = w0; g_topw[2*b+1]   = w1v;
    }
    __syncthreads();
    if (tid == 0) {
        float imp[6], ld[6];
        for (int e2 = 0; e2 < 6; e2++) {
            float si = 0.f, sl = 0.f;
            for (int b = 0; b < 8; b++) {
                si += gates[b][e2];
                sl += (gates[b][e2] > 0.f) ? 1.f : 0.f;
            }
            imp[e2] = si; ld[e2] = sl;
        }
        float mi = 0.f, ml = 0.f;
        for (int e2 = 0; e2 < 6; e2++) { mi += imp[e2]; ml += ld[e2]; }
        mi *= (1.f/6.f); ml *= (1.f/6.f);
        float vi = 0.f, vl = 0.f;
        for (int e2 = 0; e2 < 6; e2++) {
            float d = imp[e2] - mi; vi += d*d;
            d = ld[e2] - ml;       vl += d*d;
        }
        vi *= 0.2f; vl *= 0.2f;    // unbiased var, n-1 = 5
        float loss = 0.01f * (vi/(mi*mi + 1e-10f) + vl/(ml*ml + 1e-10f));
        for (long long i = BCHW; i < out_size; i++) out[i] = loss;
    }
}

// ---------------- conv1 (36->72) + exact GELU, per (b,slot) ----------------
// grid: (256 tiles of 16x16, 16 pairs). block 256 thr: 128 pixel-pairs x 2 ch-groups(36).
__global__ void __launch_bounds__(256, 1)
conv1_kernel(const float* __restrict__ x, const float* __restrict__ conv1_w) {
    extern __shared__ float smem[];
    float* ws = smem;           // 72*36*9 = 23328 floats
    float* xs = smem + 23328;   // 36*18*18 = 11664 floats
    int tile = blockIdx.x;
    int ty = (tile >> 4) << 4, tx = (tile & 15) << 4;
    int pair = blockIdx.y;
    int b = pair >> 1;
    int e = g_topidx[pair];
    int tid = threadIdx.x;

    const float* w = conv1_w + (size_t)e * 23328;   // [72][36][9]
    for (int i = tid; i < 23328; i += 256) ws[i] = w[i];
    const float* xb = x + (size_t)b * 36 * 65536;
    for (int i = tid; i < 11664; i += 256) {
        int ci = i / 324;
        int rem = i - ci*324;
        int r = rem / 18, c = rem - r*18;
        int gy = ty + r - 1, gx = tx + c - 1;
        float vv = 0.f;
        if ((unsigned)gy < 256u && (unsigned)gx < 256u) vv = xb[ci*65536 + gy*256 + gx];
        xs[i] = vv;
    }
    __syncthreads();

    int pid = tid & 127;
    int py = pid >> 3, px = (pid & 7) << 1;
    int cobase = (tid >> 7) * 36;
    float acc0[36], acc1[36];
    #pragma unroll
    for (int i = 0; i < 36; i++) { acc0[i] = 0.f; acc1[i] = 0.f; }

    #pragma unroll 1
    for (int ci = 0; ci < 36; ci++) {
        float xw[3][4];
        #pragma unroll
        for (int dy = 0; dy < 3; dy++)
            #pragma unroll
            for (int dx = 0; dx < 4; dx++)
                xw[dy][dx] = xs[ci*324 + (py+dy)*18 + (px+dx)];
        const float* wr = ws + cobase*324 + ci*9;
        #pragma unroll
        for (int co = 0; co < 36; co++) {
            const float* wc = wr + co*324;
            float a0 = acc0[co], a1 = acc1[co];
            #pragma unroll
            for (int dy = 0; dy < 3; dy++)
                #pragma unroll
                for (int dx = 0; dx < 3; dx++) {
                    float wv = wc[dy*3+dx];
                    a0 = fmaf(xw[dy][dx],   wv, a0);
                    a1 = fmaf(xw[dy][dx+1], wv, a1);
                }
            acc0[co] = a0; acc1[co] = a1;
        }
    }

    float* tb = g_t + (size_t)pair * 72 * 65536 + (size_t)((ty+py)*256 + (tx+px));
    #pragma unroll
    for (int co = 0; co < 36; co++) {
        float v0 = acc0[co], v1 = acc1[co];
        v0 = 0.5f * v0 * (1.f + erff(v0 * 0.70710678118654752f));
        v1 = 0.5f * v1 * (1.f + erff(v1 * 0.70710678118654752f));
        float2 r2; r2.x = v0; r2.y = v1;
        *reinterpret_cast<float2*>(tb + (size_t)(cobase+co) * 65536) = r2;
    }
}

// ---------------- conv2 (72->36) with gate-weighted combine over 2 slots ----
// grid: (256 tiles, 8 batch). block 256 thr: 128 pixel-pairs x 2 ch-groups(18).
__global__ void __launch_bounds__(256, 1)
conv2_kernel(float* __restrict__ out, const float* __restrict__ conv2_w) {
    extern __shared__ float smem[];
    float* ws = smem;           // 36*72*9 = 23328 floats
    float* ts = smem + 23328;   // 72*18*18 = 23328 floats
    int tile = blockIdx.x;
    int ty = (tile >> 4) << 4, tx = (tile & 15) << 4;
    int b = blockIdx.y;
    int tid = threadIdx.x;
    int pid = tid & 127;
    int py = pid >> 3, px = (pid & 7) << 1;
    int cobase = (tid >> 7) * 18;
    float acc0[18], acc1[18];
    #pragma unroll
    for (int i = 0; i < 18; i++) { acc0[i] = 0.f; acc1[i] = 0.f; }

    for (int slot = 0; slot < 2; slot++) {
        int pair = b*2 + slot;
        int e = g_topidx[pair];
        float gw = g_topw[pair];
        if (slot) __syncthreads();          // protect smem from prior iteration
        const float* w = conv2_w + (size_t)e * 23328;   // [36][72][9]
        for (int i = tid; i < 23328; i += 256) ws[i] = w[i];
        const float* tb = g_t + (size_t)pair * 72 * 65536;
        for (int i = tid; i < 23328; i += 256) {
            int ci = i / 324;
            int rem = i - ci*324;
            int r = rem / 18, c = rem - r*18;
            int gy = ty + r - 1, gx = tx + c - 1;
            float vv = 0.f;
            if ((unsigned)gy < 256u && (unsigned)gx < 256u) vv = tb[ci*65536 + gy*256 + gx];
            ts[i] = vv;
        }
        __syncthreads();

        #pragma unroll 1
        for (int ci = 0; ci < 72; ci++) {
            float xw[3][4];
            #pragma unroll
            for (int dy = 0; dy < 3; dy++)
                #pragma unroll
                for (int dx = 0; dx < 4; dx++)
                    xw[dy][dx] = gw * ts[ci*324 + (py+dy)*18 + (px+dx)];
            const float* wr = ws + cobase*648 + ci*9;
            #pragma unroll
            for (int co = 0; co < 18; co++) {
                const float* wc = wr + co*648;
                float a0 = acc0[co], a1 = acc1[co];
                #pragma unroll
                for (int dy = 0; dy < 3; dy++)
                    #pragma unroll
                    for (int dx = 0; dx < 3; dx++) {
                        float wv = wc[dy*3+dx];
                        a0 = fmaf(xw[dy][dx],   wv, a0);
                        a1 = fmaf(xw[dy][dx+1], wv, a1);
                    }
                acc0[co] = a0; acc1[co] = a1;
            }
        }
    }

    float* op = out + (size_t)b * 36 * 65536 + (size_t)((ty+py)*256 + (tx+px));
    #pragma unroll
    for (int co = 0; co < 18; co++) {
        float2 r2; r2.x = acc0[co]; r2.y = acc1[co];
        *reinterpret_cast<float2*>(op + (size_t)(cobase+co) * 65536) = r2;
    }
}

// ---------------- launcher ----------------
extern "C" void kernel_launch(void* const* d_in, const int* in_sizes, int n_in,
                              void* d_out, int out_size) {
    const float* x       = (const float*)d_in[0];
    const float* timev   = (const float*)d_in[1];
    const float* time_w  = (const float*)d_in[2];
    const float* time_b  = (const float*)d_in[3];
    const float* gate_w1 = (const float*)d_in[4];
    const float* gate_b1 = (const float*)d_in[5];
    const float* gate_w2 = (const float*)d_in[6];
    const float* gate_b2 = (const float*)d_in[7];
    const float* conv1_w = (const float*)d_in[8];
    const float* conv2_w = (const float*)d_in[9];
    float* out = (float*)d_out;

    cudaFuncSetAttribute(conv1_kernel, cudaFuncAttributeMaxDynamicSharedMemorySize, 139968);
    cudaFuncSetAttribute(conv2_kernel, cudaFuncAttributeMaxDynamicSharedMemorySize, 186624);

    pool_kernel<<<288, 256>>>(x);
    gate_kernel<<<1, 256>>>(timev, time_w, time_b, gate_w1, gate_b1,
                            gate_w2, gate_b2, out, (long long)out_size);
    conv1_kernel<<<dim3(256, 16), 256, 139968>>>(x, conv1_w);
    conv2_kernel<<<dim3(256, 8),  256, 186624>>>(out, conv2_w);
}

// round 4
// speedup vs baseline: 1.0710x; 1.0710x over previous
#include <cuda_runtime.h>
#include <math.h>

typedef unsigned long long u64;

#define BCHW (8*36*256*256)

// ---------------- device scratch ----------------
__device__ float g_t[16ull*72ull*65536ull];   // gelu(conv1) per (b,slot): 302 MB
__device__ float g_avg[288];
__device__ float g_max[288];
__device__ int   g_topidx[16];
__device__ float g_topw[16];

// ---------------- f32x2 helpers ----------------
__device__ __forceinline__ u64 ffma2(u64 a, u64 b, u64 c) {
    u64 d;
    asm("fma.rn.f32x2 %0, %1, %2, %3;" : "=l"(d) : "l"(a), "l"(b), "l"(c));
    return d;
}
__device__ __forceinline__ u64 pack2(unsigned lo, unsigned hi) {
    u64 d; asm("mov.b64 %0, {%1, %2};" : "=l"(d) : "r"(lo), "r"(hi)); return d;
}
__device__ __forceinline__ void unpack2(u64 v, unsigned &lo, unsigned &hi) {
    asm("mov.b64 {%0, %1}, %2;" : "=r"(lo), "=r"(hi) : "l"(v));
}
__device__ __forceinline__ u64 midpair(u64 a, u64 b) {
    unsigned alo, ahi, blo, bhi;
    unpack2(a, alo, ahi); unpack2(b, blo, bhi);
    return pack2(ahi, blo);
}
__device__ __forceinline__ float gelu_exact(float v) {
    return 0.5f * v * (1.f + erff(v * 0.70710678118654752f));
}

// ---------------- pooling ----------------
__global__ void pool_kernel(const float* __restrict__ x) {
    int bc = blockIdx.x;
    const float4* p = reinterpret_cast<const float4*>(x + (size_t)bc * 65536);
    float s = 0.f, m = -3.402823466e38f;
    for (int i = threadIdx.x; i < 16384; i += 256) {
        float4 v = p[i];
        s += (v.x + v.y) + (v.z + v.w);
        m = fmaxf(m, fmaxf(fmaxf(v.x, v.y), fmaxf(v.z, v.w)));
    }
    __shared__ float ss[256], sm2[256];
    ss[threadIdx.x] = s; sm2[threadIdx.x] = m;
    __syncthreads();
    for (int o = 128; o > 0; o >>= 1) {
        if (threadIdx.x < o) {
            ss[threadIdx.x] += ss[threadIdx.x + o];
            sm2[threadIdx.x] = fmaxf(sm2[threadIdx.x], sm2[threadIdx.x + o]);
        }
        __syncthreads();
    }
    if (threadIdx.x == 0) { g_avg[bc] = ss[0] * (1.f/65536.f); g_max[bc] = sm2[0]; }
}

// ---------------- gating MLP + top-2 + loss ----------------
__global__ void gate_kernel(const float* __restrict__ timev,
                            const float* __restrict__ time_w,
                            const float* __restrict__ time_b,
                            const float* __restrict__ w1,
                            const float* __restrict__ b1,
                            const float* __restrict__ w2,
                            const float* __restrict__ b2,
                            float* __restrict__ out, long long out_size) {
    __shared__ float v[8][72];
    __shared__ float h[8][72];
    __shared__ float lg[8][6];
    __shared__ float gates[8][6];
    int tid = threadIdx.x;
    if (tid < 48) gates[tid/6][tid%6] = 0.f;
    for (int i = tid; i < 576; i += 256) {
        int b = i / 72, j = i % 72;
        float a = (j < 36) ? g_avg[b*36 + j] : g_max[b*36 + j - 36];
        float s = time_b[j];
        #pragma unroll
        for (int k = 0; k < 32; k++) s = fmaf(timev[b*32+k], time_w[k*72+j], s);
        v[b][j] = a + s;
    }
    __syncthreads();
    for (int i = tid; i < 576; i += 256) {
        int b = i / 72, j = i % 72;
        float s = b1[j];
        for (int k = 0; k < 72; k++) s = fmaf(v[b][k], w1[k*72+j], s);
        h[b][j] = (s > 0.f) ? s : 0.01f * s;
    }
    __syncthreads();
    if (tid < 48) {
        int b = tid / 6, j = tid % 6;
        float s = b2[j];
        for (int k = 0; k < 72; k++) s = fmaf(h[b][k], w2[k*6+j], s);
        lg[b][j] = s;
    }
    __syncthreads();
    if (tid < 8) {
        int b = tid;
        float v0 = -3.402823466e38f; int i0 = 0;
        for (int j = 0; j < 6; j++) if (lg[b][j] > v0) { v0 = lg[b][j]; i0 = j; }
        float v1 = -3.402823466e38f; int i1 = 0;
        for (int j = 0; j < 6; j++) if (j != i0 && lg[b][j] > v1) { v1 = lg[b][j]; i1 = j; }
        float e  = expf(v1 - v0);
        float w0 = 1.f / (1.f + e);
        float w1v = e / (1.f + e);
        gates[b][i0] = w0; gates[b][i1] = w1v;
        g_topidx[2*b]   = i0; g_topidx[2*b+1] = i1;
        g_topw[2*b]     = w0; g_topw[2*b+1]   = w1v;
    }
    __syncthreads();
    if (tid == 0) {
        float imp[6], ld[6];
        for (int e2 = 0; e2 < 6; e2++) {
            float si = 0.f, sl = 0.f;
            for (int b = 0; b < 8; b++) {
                si += gates[b][e2];
                sl += (gates[b][e2] > 0.f) ? 1.f : 0.f;
            }
            imp[e2] = si; ld[e2] = sl;
        }
        float mi = 0.f, ml = 0.f;
        for (int e2 = 0; e2 < 6; e2++) { mi += imp[e2]; ml += ld[e2]; }
        mi *= (1.f/6.f); ml *= (1.f/6.f);
        float vi = 0.f, vl = 0.f;
        for (int e2 = 0; e2 < 6; e2++) {
            float d = imp[e2] - mi; vi += d*d;
            d = ld[e2] - ml;       vl += d*d;
        }
        vi *= 0.2f; vl *= 0.2f;
        float loss = 0.01f * (vi/(mi*mi + 1e-10f) + vl/(ml*ml + 1e-10f));
        for (long long i = BCHW; i < out_size; i++) out[i] = loss;
    }
}

// SMEM layout (both convs): wd = u64[11664] (36co x 324 taps, duplicated pairs),
// ts = float[36ci][18 rows][stride 20]. Total 145152 bytes.
#define SMEM_BYTES 145152

// Thread mapping: pxg = tid&63 -> 2x2 pixel quad (2 pixel-pairs), cog = tid>>6 -> 9 out-ch.
// Per ci: load 4 rows x {aligned pair, aligned pair} LDS.64 + 1 mid pack per row,
// then 9co x 9tap x 2pairs FFMA2.

// ---------------- conv1 (36->72) + exact GELU ----------------
__global__ void __launch_bounds__(256, 1)
conv1_kernel(const float* __restrict__ x, const float* __restrict__ conv1_w) {
    extern __shared__ float smem[];
    u64*   wd = (u64*)smem;          // 11664 u64
    float* ts = smem + 23328;        // 12960 floats
    int tile = blockIdx.x;
    int ty = (tile >> 4) << 4, tx = (tile & 15) << 4;
    int pair = blockIdx.y;
    int b = pair >> 1;
    int e = g_topidx[pair];
    int tid = threadIdx.x;
    int pxg = tid & 63, cog = tid >> 6;
    int pc = (pxg & 7) * 2, pr = (pxg >> 3) * 2;

    // input tile (loaded once, reused by both co-passes)
    const float* xb = x + (size_t)b * 36 * 65536;
    for (int i = tid; i < 11664; i += 256) {
        int ci = i / 324, rem = i - ci*324;
        int r = rem / 18, c = rem - r*18;
        int gy = ty + r - 1, gx = tx + c - 1;
        float v = 0.f;
        if ((unsigned)gy < 256u && (unsigned)gx < 256u) v = xb[ci*65536 + gy*256 + gx];
        ts[ci*360 + r*20 + c] = v;
    }

    const float* wbase = conv1_w + (size_t)e * 23328;   // [72][36][9]
    float* gb = g_t + (size_t)pair * 72 * 65536;
    const u64* tsu = (const u64*)ts;
    int wbaseoff = pr*10 + (pc >> 1);

    for (int pass = 0; pass < 2; pass++) {
        __syncthreads();
        const float* wp0 = wbase + pass * 36 * 324;
        for (int i = tid; i < 11664; i += 256) {
            int co = i / 324, rem = i - co*324;
            unsigned bits = __float_as_uint(wp0[co*324 + rem]);
            wd[rem*36 + co] = pack2(bits, bits);
        }
        __syncthreads();

        u64 acc[9][2];
        #pragma unroll
        for (int i = 0; i < 9; i++) { acc[i][0] = 0ull; acc[i][1] = 0ull; }

        u64 xr[4][3];
        #pragma unroll
        for (int r4 = 0; r4 < 4; r4++) {
            u64 a  = tsu[(r4)*10 + wbaseoff];
            u64 bb = tsu[(r4)*10 + wbaseoff + 1];
            xr[r4][0] = a; xr[r4][2] = bb; xr[r4][1] = midpair(a, bb);
        }

        #pragma unroll 1
        for (int ci = 0; ci < 36; ci++) {
            u64 xn[4][3];
            if (ci < 35) {
                const u64* tn = tsu + (ci + 1) * 180;
                #pragma unroll
                for (int r4 = 0; r4 < 4; r4++) {
                    u64 a  = tn[r4*10 + wbaseoff];
                    u64 bb = tn[r4*10 + wbaseoff + 1];
                    xn[r4][0] = a; xn[r4][2] = bb; xn[r4][1] = midpair(a, bb);
                }
            }
            const u64* wci = wd + ci*324 + cog*9;
            #pragma unroll
            for (int co9 = 0; co9 < 9; co9++) {
                const u64* wcp = wci + co9;
                #pragma unroll
                for (int dy = 0; dy < 3; dy++)
                    #pragma unroll
                    for (int dx = 0; dx < 3; dx++) {
                        u64 w2 = wcp[(dy*3 + dx) * 36];
                        acc[co9][0] = ffma2(xr[dy][dx],     w2, acc[co9][0]);
                        acc[co9][1] = ffma2(xr[dy+1][dx],   w2, acc[co9][1]);
                    }
            }
            if (ci < 35) {
                #pragma unroll
                for (int r4 = 0; r4 < 4; r4++)
                    #pragma unroll
                    for (int dx = 0; dx < 3; dx++) xr[r4][dx] = xn[r4][dx];
            }
        }

        // epilogue: exact GELU + store pairs
        int row0 = ty + pr, col = tx + pc;
        #pragma unroll
        for (int co9 = 0; co9 < 9; co9++) {
            int ch = pass*36 + cog*9 + co9;
            #pragma unroll
            for (int p2 = 0; p2 < 2; p2++) {
                unsigned lo, hi; unpack2(acc[co9][p2], lo, hi);
                float v0 = gelu_exact(__uint_as_float(lo));
                float v1 = gelu_exact(__uint_as_float(hi));
                *(u64*)(gb + (size_t)ch*65536 + (size_t)(row0 + p2)*256 + col) =
                    pack2(__float_as_uint(v0), __float_as_uint(v1));
            }
        }
    }
}

// ---------------- conv2 (72->36), gate-weighted combine over 2 slots ----------------
__global__ void __launch_bounds__(256, 1)
conv2_kernel(float* __restrict__ out, const float* __restrict__ conv2_w) {
    extern __shared__ float smem[];
    u64*   wd = (u64*)smem;
    float* ts = smem + 23328;
    int tile = blockIdx.x;
    int ty = (tile >> 4) << 4, tx = (tile & 15) << 4;
    int b = blockIdx.y;
    int tid = threadIdx.x;
    int pxg = tid & 63, cog = tid >> 6;
    int pc = (pxg & 7) * 2, pr = (pxg >> 3) * 2;
    int wbaseoff = pr*10 + (pc >> 1);
    const u64* tsu = (const u64*)ts;

    u64 acc[9][2];
    #pragma unroll
    for (int i = 0; i < 9; i++) { acc[i][0] = 0ull; acc[i][1] = 0ull; }

    for (int stage = 0; stage < 4; stage++) {
        int slot = stage >> 1, cih = stage & 1;
        int pair = b*2 + slot;
        int e = g_topidx[pair];
        float gw = g_topw[pair];
        __syncthreads();
        // weights: conv2_w[e][co][cih*36+ci][k], duplicated pairs
        const float* wb = conv2_w + (size_t)e * 23328 + cih * 324;
        for (int i = tid; i < 11664; i += 256) {
            int co = i / 324, rem = i - co*324;
            unsigned bits = __float_as_uint(wb[co*648 + rem]);
            wd[rem*36 + co] = pack2(bits, bits);
        }
        // tile: gelu(conv1) channels [cih*36, cih*36+36), pre-scaled by gate weight
        const float* tb = g_t + (size_t)pair * 72 * 65536 + (size_t)cih * 36 * 65536;
        for (int i = tid; i < 11664; i += 256) {
            int ci = i / 324, rem = i - ci*324;
            int r = rem / 18, c = rem - r*18;
            int gy = ty + r - 1, gx = tx + c - 1;
            float v = 0.f;
            if ((unsigned)gy < 256u && (unsigned)gx < 256u) v = tb[ci*65536 + gy*256 + gx];
            ts[ci*360 + r*20 + c] = gw * v;
        }
        __syncthreads();

        u64 xr[4][3];
        #pragma unroll
        for (int r4 = 0; r4 < 4; r4++) {
            u64 a  = tsu[r4*10 + wbaseoff];
            u64 bb = tsu[r4*10 + wbaseoff + 1];
            xr[r4][0] = a; xr[r4][2] = bb; xr[r4][1] = midpair(a, bb);
        }

        #pragma unroll 1
        for (int ci = 0; ci < 36; ci++) {
            u64 xn[4][3];
            if (ci < 35) {
                const u64* tn = tsu + (ci + 1) * 180;
                #pragma unroll
                for (int r4 = 0; r4 < 4; r4++) {
                    u64 a  = tn[r4*10 + wbaseoff];
                    u64 bb = tn[r4*10 + wbaseoff + 1];
                    xn[r4][0] = a; xn[r4][2] = bb; xn[r4][1] = midpair(a, bb);
                }
            }
            const u64* wci = wd + ci*324 + cog*9;
            #pragma unroll
            for (int co9 = 0; co9 < 9; co9++) {
                const u64* wcp = wci + co9;
                #pragma unroll
                for (int dy = 0; dy < 3; dy++)
                    #pragma unroll
                    for (int dx = 0; dx < 3; dx++) {
                        u64 w2 = wcp[(dy*3 + dx) * 36];
                        acc[co9][0] = ffma2(xr[dy][dx],   w2, acc[co9][0]);
                        acc[co9][1] = ffma2(xr[dy+1][dx], w2, acc[co9][1]);
                    }
            }
            if (ci < 35) {
                #pragma unroll
                for (int r4 = 0; r4 < 4; r4++)
                    #pragma unroll
                    for (int dx = 0; dx < 3; dx++) xr[r4][dx] = xn[r4][dx];
            }
        }
    }

    // store: both slots accumulated, gate weights already folded in
    float* ob = out + (size_t)b * 36 * 65536;
    int row0 = ty + pr, col = tx + pc;
    #pragma unroll
    for (int co9 = 0; co9 < 9; co9++) {
        int ch = cog*9 + co9;
        #pragma unroll
        for (int p2 = 0; p2 < 2; p2++) {
            *(u64*)(ob + (size_t)ch*65536 + (size_t)(row0 + p2)*256 + col) = acc[co9][p2];
        }
    }
}

// ---------------- launcher ----------------
extern "C" void kernel_launch(void* const* d_in, const int* in_sizes, int n_in,
                              void* d_out, int out_size) {
    const float* x       = (const float*)d_in[0];
    const float* timev   = (const float*)d_in[1];
    const float* time_w  = (const float*)d_in[2];
    const float* time_b  = (const float*)d_in[3];
    const float* gate_w1 = (const float*)d_in[4];
    const float* gate_b1 = (const float*)d_in[5];
    const float* gate_w2 = (const float*)d_in[6];
    const float* gate_b2 = (const float*)d_in[7];
    const float* conv1_w = (const float*)d_in[8];
    const float* conv2_w = (const float*)d_in[9];
    float* out = (float*)d_out;

    cudaFuncSetAttribute(conv1_kernel, cudaFuncAttributeMaxDynamicSharedMemorySize, SMEM_BYTES);
    cudaFuncSetAttribute(conv2_kernel, cudaFuncAttributeMaxDynamicSharedMemorySize, SMEM_BYTES);

    pool_kernel<<<288, 256>>>(x);
    gate_kernel<<<1, 256>>>(timev, time_w, time_b, gate_w1, gate_b1,
                            gate_w2, gate_b2, out, (long long)out_size);
    conv1_kernel<<<dim3(256, 16), 256, SMEM_BYTES>>>(x, conv1_w);
    conv2_kernel<<<dim3(256, 8),  256, SMEM_BYTES>>>(out, conv2_w);
}

// round 5
// speedup vs baseline: 1.7067x; 1.5936x over previous
#include <cuda_runtime.h>
#include <math.h>

typedef unsigned long long u64;

#define BCHW (8*36*256*256)

// ---------------- device scratch ----------------
__device__ float g_t[16ull*72ull*65536ull];   // gelu(conv1) per (b,slot): 302 MB
__device__ float g_avg[288];
__device__ float g_max[288];
__device__ int   g_topidx[16];
__device__ float g_topw[16];

// ---------------- f32x2 helpers ----------------
__device__ __forceinline__ u64 ffma2(u64 a, u64 b, u64 c) {
    u64 d;
    asm("fma.rn.f32x2 %0, %1, %2, %3;" : "=l"(d) : "l"(a), "l"(b), "l"(c));
    return d;
}
__device__ __forceinline__ u64 pack2(unsigned lo, unsigned hi) {
    u64 d; asm("mov.b64 %0, {%1, %2};" : "=l"(d) : "r"(lo), "r"(hi)); return d;
}
__device__ __forceinline__ void unpack2(u64 v, unsigned &lo, unsigned &hi) {
    asm("mov.b64 {%0, %1}, %2;" : "=r"(lo), "=r"(hi) : "l"(v));
}
__device__ __forceinline__ float gelu_exact(float v) {
    return 0.5f * v * (1.f + erff(v * 0.70710678118654752f));
}

// ---------------- pooling ----------------
__global__ void pool_kernel(const float* __restrict__ x) {
    int bc = blockIdx.x;
    const float4* p = reinterpret_cast<const float4*>(x + (size_t)bc * 65536);
    float s = 0.f, m = -3.402823466e38f;
    for (int i = threadIdx.x; i < 16384; i += 256) {
        float4 v = p[i];
        s += (v.x + v.y) + (v.z + v.w);
        m = fmaxf(m, fmaxf(fmaxf(v.x, v.y), fmaxf(v.z, v.w)));
    }
    __shared__ float ss[256], sm2[256];
    ss[threadIdx.x] = s; sm2[threadIdx.x] = m;
    __syncthreads();
    for (int o = 128; o > 0; o >>= 1) {
        if (threadIdx.x < o) {
            ss[threadIdx.x] += ss[threadIdx.x + o];
            sm2[threadIdx.x] = fmaxf(sm2[threadIdx.x], sm2[threadIdx.x + o]);
        }
        __syncthreads();
    }
    if (threadIdx.x == 0) { g_avg[bc] = ss[0] * (1.f/65536.f); g_max[bc] = sm2[0]; }
}

// ---------------- gating MLP + top-2 + loss ----------------
__global__ void gate_kernel(const float* __restrict__ timev,
                            const float* __restrict__ time_w,
                            const float* __restrict__ time_b,
                            const float* __restrict__ w1,
                            const float* __restrict__ b1,
                            const float* __restrict__ w2,
                            const float* __restrict__ b2,
                            float* __restrict__ out, long long out_size) {
    __shared__ float v[8][72];
    __shared__ float h[8][72];
    __shared__ float lg[8][6];
    __shared__ float gates[8][6];
    int tid = threadIdx.x;
    if (tid < 48) gates[tid/6][tid%6] = 0.f;
    for (int i = tid; i < 576; i += 256) {
        int b = i / 72, j = i % 72;
        float a = (j < 36) ? g_avg[b*36 + j] : g_max[b*36 + j - 36];
        float s = time_b[j];
        #pragma unroll
        for (int k = 0; k < 32; k++) s = fmaf(timev[b*32+k], time_w[k*72+j], s);
        v[b][j] = a + s;
    }
    __syncthreads();
    for (int i = tid; i < 576; i += 256) {
        int b = i / 72, j = i % 72;
        float s = b1[j];
        for (int k = 0; k < 72; k++) s = fmaf(v[b][k], w1[k*72+j], s);
        h[b][j] = (s > 0.f) ? s : 0.01f * s;
    }
    __syncthreads();
    if (tid < 48) {
        int b = tid / 6, j = tid % 6;
        float s = b2[j];
        for (int k = 0; k < 72; k++) s = fmaf(h[b][k], w2[k*6+j], s);
        lg[b][j] = s;
    }
    __syncthreads();
    if (tid < 8) {
        int b = tid;
        float v0 = -3.402823466e38f; int i0 = 0;
        for (int j = 0; j < 6; j++) if (lg[b][j] > v0) { v0 = lg[b][j]; i0 = j; }
        float v1 = -3.402823466e38f; int i1 = 0;
        for (int j = 0; j < 6; j++) if (j != i0 && lg[b][j] > v1) { v1 = lg[b][j]; i1 = j; }
        float e  = expf(v1 - v0);
        float w0 = 1.f / (1.f + e);
        float w1v = e / (1.f + e);
        gates[b][i0] = w0; gates[b][i1] = w1v;
        g_topidx[2*b]   = i0; g_topidx[2*b+1] = i1;
        g_topw[2*b]     = w0; g_topw[2*b+1]   = w1v;
    }
    __syncthreads();
    if (tid == 0) {
        float imp[6], ld[6];
        for (int e2 = 0; e2 < 6; e2++) {
            float si = 0.f, sl = 0.f;
            for (int b = 0; b < 8; b++) {
                si += gates[b][e2];
                sl += (gates[b][e2] > 0.f) ? 1.f : 0.f;
            }
            imp[e2] = si; ld[e2] = sl;
        }
        float mi = 0.f, ml = 0.f;
        for (int e2 = 0; e2 < 6; e2++) { mi += imp[e2]; ml += ld[e2]; }
        mi *= (1.f/6.f); ml *= (1.f/6.f);
        float vi = 0.f, vl = 0.f;
        for (int e2 = 0; e2 < 6; e2++) {
            float d = imp[e2] - mi; vi += d*d;
            d = ld[e2] - ml;       vl += d*d;
        }
        vi *= 0.2f; vl *= 0.2f;
        float loss = 0.01f * (vi/(mi*mi + 1e-10f) + vl/(ml*ml + 1e-10f));
        for (long long i = BCHW; i < out_size; i++) out[i] = loss;
    }
}

// SMEM: wd = u64[5832]  (324 taps x 18 co-pairs, natural (co,co+1) pairs) = 46656 B
//       ts = float[36ci][18 rows][stride 20]                              = 51840 B
// total 98496 B -> 2 CTAs/SM.
#define SMEM_BYTES 98496

// Thread map: pairid = tid&127 -> (ro = pairid>>3 in 0..15, p = pairid&7 -> cols 2p,2p+1)
//             cg = tid>>7 -> which 18-co half (9 co-pairs).
// Per ci: 6 LDS.64 (3x4 window, halo-aligned) + 12 dup packs + 81 LDS.64 w-broadcast
//         + 162 FFMA2 (9 taps x 9 co-pairs x 2 pixels).

// ---------------- conv1 (36->72) + exact GELU ----------------
__global__ void __launch_bounds__(256, 2)
conv1_kernel(const float* __restrict__ x, const float* __restrict__ conv1_w) {
    extern __shared__ float smem[];
    u64*   wd = (u64*)smem;          // 5832 u64
    float* ts = smem + 11664;        // 12960 floats
    int tile = blockIdx.x;
    int ty = (tile >> 4) << 4, tx = (tile & 15) << 4;
    int pair = blockIdx.y;
    int b = pair >> 1;
    int e = g_topidx[pair];
    int tid = threadIdx.x;
    int pairid = tid & 127, cg = tid >> 7;
    int ro = pairid >> 3, p = pairid & 7;

    // stage input tile once (reused by both co passes)
    const float* xb = x + (size_t)b * 36 * 65536;
    for (int i = tid; i < 11664; i += 256) {
        int ci = i / 324, rem = i - ci*324;
        int r = rem / 18, c = rem - r*18;
        int gy = ty + r - 1, gx = tx + c - 1;
        float v = 0.f;
        if ((unsigned)gy < 256u && (unsigned)gx < 256u) v = xb[ci*65536 + gy*256 + gx];
        ts[ci*360 + r*20 + c] = v;
    }

    const float* wbase = conv1_w + (size_t)e * 23328;   // [72][36][9]
    float* gb = g_t + (size_t)pair * 72 * 65536;
    const u64* tsu = (const u64*)ts;
    const u64* tci = tsu + ro*10 + p;   // row/col base within a ci-plane

    for (int pass = 0; pass < 2; pass++) {
        __syncthreads();
        // weights: wd[tapci*18 + cp] = (w[co], w[co+1]), co = pass*36 + 2*cp
        for (int i = tid; i < 5832; i += 256) {
            int tapci = i / 18, cp = i - tapci*18;
            const float* wp = wbase + (size_t)(pass*36 + cp*2) * 324 + tapci;
            wd[i] = pack2(__float_as_uint(wp[0]), __float_as_uint(wp[324]));
        }
        __syncthreads();

        u64 acc[9][2];
        #pragma unroll
        for (int i = 0; i < 9; i++) { acc[i][0] = 0ull; acc[i][1] = 0ull; }

        #pragma unroll 1
        for (int ci = 0; ci < 36; ci++) {
            // 3x4 input window: 2 aligned u64 per row (halo makes it aligned)
            u64 dup[3][4];
            #pragma unroll
            for (int r = 0; r < 3; r++) {
                u64 a = tci[ci*180 + r*10];
                u64 bb = tci[ci*180 + r*10 + 1];
                unsigned a0, a1, a2, a3;
                unpack2(a, a0, a1); unpack2(bb, a2, a3);
                dup[r][0] = pack2(a0, a0); dup[r][1] = pack2(a1, a1);
                dup[r][2] = pack2(a2, a2); dup[r][3] = pack2(a3, a3);
            }
            const u64* wci = wd + ci*162 + cg*9;
            #pragma unroll
            for (int dy = 0; dy < 3; dy++)
                #pragma unroll
                for (int dx = 0; dx < 3; dx++) {
                    const u64* wp2 = wci + (dy*3 + dx)*18;
                    #pragma unroll
                    for (int cp = 0; cp < 9; cp++) {
                        u64 w2 = wp2[cp];
                        acc[cp][0] = ffma2(dup[dy][dx],   w2, acc[cp][0]);
                        acc[cp][1] = ffma2(dup[dy][dx+1], w2, acc[cp][1]);
                    }
                }
        }

        // epilogue: exact GELU, re-pack pixel-major, coalesced STG.64
        float* gp = gb + (size_t)(ty + ro)*256 + (tx + 2*p);
        #pragma unroll
        for (int cp = 0; cp < 9; cp++) {
            int ch = pass*36 + (cg*9 + cp)*2;
            unsigned p0c0, p0c1, p1c0, p1c1;
            unpack2(acc[cp][0], p0c0, p0c1);
            unpack2(acc[cp][1], p1c0, p1c1);
            float a = gelu_exact(__uint_as_float(p0c0));
            float bq = gelu_exact(__uint_as_float(p1c0));
            float c = gelu_exact(__uint_as_float(p0c1));
            float d = gelu_exact(__uint_as_float(p1c1));
            *(u64*)(gp + (size_t)ch*65536)     = pack2(__float_as_uint(a), __float_as_uint(bq));
            *(u64*)(gp + (size_t)(ch+1)*65536) = pack2(__float_as_uint(c), __float_as_uint(d));
        }
    }
}

// ---------------- conv2 (72->36), gate-weighted combine over 2 slots ----------------
__global__ void __launch_bounds__(256, 2)
conv2_kernel(float* __restrict__ out, const float* __restrict__ conv2_w) {
    extern __shared__ float smem[];
    u64*   wd = (u64*)smem;
    float* ts = smem + 11664;
    int tile = blockIdx.x;
    int ty = (tile >> 4) << 4, tx = (tile & 15) << 4;
    int b = blockIdx.y;
    int tid = threadIdx.x;
    int pairid = tid & 127, cg = tid >> 7;
    int ro = pairid >> 3, p = pairid & 7;
    const u64* tsu = (const u64*)ts;
    const u64* tci = tsu + ro*10 + p;

    u64 acc[9][2];
    #pragma unroll
    for (int i = 0; i < 9; i++) { acc[i][0] = 0ull; acc[i][1] = 0ull; }

    for (int stage = 0; stage < 4; stage++) {
        int slot = stage >> 1, cih = stage & 1;
        int pair = b*2 + slot;
        int e = g_topidx[pair];
        float gw = g_topw[pair];
        __syncthreads();
        // weights: conv2_w[e][co][cih*36+ci][tap]; wd[tapci*18+cp] = (w[2cp], w[2cp+1])
        const float* wb = conv2_w + (size_t)e * 23328 + cih * 324;
        for (int i = tid; i < 5832; i += 256) {
            int tapci = i / 18, cp = i - tapci*18;
            const float* wp = wb + (size_t)(cp*2) * 648 + tapci;
            wd[i] = pack2(__float_as_uint(wp[0]), __float_as_uint(wp[648]));
        }
        // tile: gelu(conv1) channels [cih*36, cih*36+36), pre-scaled by gate weight
        const float* tb = g_t + (size_t)pair * 72 * 65536 + (size_t)cih * 36 * 65536;
        for (int i = tid; i < 11664; i += 256) {
            int ci = i / 324, rem = i - ci*324;
            int r = rem / 18, c = rem - r*18;
            int gy = ty + r - 1, gx = tx + c - 1;
            float v = 0.f;
            if ((unsigned)gy < 256u && (unsigned)gx < 256u) v = tb[ci*65536 + gy*256 + gx];
            ts[ci*360 + r*20 + c] = gw * v;
        }
        __syncthreads();

        #pragma unroll 1
        for (int ci = 0; ci < 36; ci++) {
            u64 dup[3][4];
            #pragma unroll
            for (int r = 0; r < 3; r++) {
                u64 a = tci[ci*180 + r*10];
                u64 bb = tci[ci*180 + r*10 + 1];
                unsigned a0, a1, a2, a3;
                unpack2(a, a0, a1); unpack2(bb, a2, a3);
                dup[r][0] = pack2(a0, a0); dup[r][1] = pack2(a1, a1);
                dup[r][2] = pack2(a2, a2); dup[r][3] = pack2(a3, a3);
            }
            const u64* wci = wd + ci*162 + cg*9;
            #pragma unroll
            for (int dy = 0; dy < 3; dy++)
                #pragma unroll
                for (int dx = 0; dx < 3; dx++) {
                    const u64* wp2 = wci + (dy*3 + dx)*18;
                    #pragma unroll
                    for (int cp = 0; cp < 9; cp++) {
                        u64 w2 = wp2[cp];
                        acc[cp][0] = ffma2(dup[dy][dx],   w2, acc[cp][0]);
                        acc[cp][1] = ffma2(dup[dy][dx+1], w2, acc[cp][1]);
                    }
                }
        }
    }

    // store: both slots accumulated, gate weights folded in; pixel-major repack
    float* op = out + (size_t)b * 36 * 65536 + (size_t)(ty + ro)*256 + (tx + 2*p);
    #pragma unroll
    for (int cp = 0; cp < 9; cp++) {
        int ch = (cg*9 + cp)*2;
        unsigned p0c0, p0c1, p1c0, p1c1;
        unpack2(acc[cp][0], p0c0, p0c1);
        unpack2(acc[cp][1], p1c0, p1c1);
        *(u64*)(op + (size_t)ch*65536)     = pack2(p0c0, p1c0);
        *(u64*)(op + (size_t)(ch+1)*65536) = pack2(p0c1, p1c1);
    }
}

// ---------------- launcher ----------------
extern "C" void kernel_launch(void* const* d_in, const int* in_sizes, int n_in,
                              void* d_out, int out_size) {
    const float* x       = (const float*)d_in[0];
    const float* timev   = (const float*)d_in[1];
    const float* time_w  = (const float*)d_in[2];
    const float* time_b  = (const float*)d_in[3];
    const float* gate_w1 = (const float*)d_in[4];
    const float* gate_b1 = (const float*)d_in[5];
    const float* gate_w2 = (const float*)d_in[6];
    const float* gate_b2 = (const float*)d_in[7];
    const float* conv1_w = (const float*)d_in[8];
    const float* conv2_w = (const float*)d_in[9];
    float* out = (float*)d_out;

    cudaFuncSetAttribute(conv1_kernel, cudaFuncAttributeMaxDynamicSharedMemorySize, SMEM_BYTES);
    cudaFuncSetAttribute(conv2_kernel, cudaFuncAttributeMaxDynamicSharedMemorySize, SMEM_BYTES);

    pool_kernel<<<288, 256>>>(x);
    gate_kernel<<<1, 256>>>(timev, time_w, time_b, gate_w1, gate_b1,
                            gate_w2, gate_b2, out, (long long)out_size);
    conv1_kernel<<<dim3(256, 16), 256, SMEM_BYTES>>>(x, conv1_w);
    conv2_kernel<<<dim3(256, 8),  256, SMEM_BYTES>>>(out, conv2_w);
}